// round 16
// baseline (speedup 1.0000x reference)
#include <cuda_runtime.h>
#include <cstdint>
#include <math.h>

// Problem constants (fixed shapes from setup_inputs)
#define NB 2
#define CH 128
#define HH 128
#define WW 128
#define HL 64
#define WL 64
#define PLANE (HH*WW)          // 16384
#define IMG   (CH*PLANE)

#define NSPLIT 4               // channel splits for gating conv
#define CPS (CH/NSPLIT)        // 32
#define NGRP 8                 // channel groups for sim/agg
#define GSIM (CH/NGRP)         // 16

// Scratch (module-load allocated; no runtime allocs)
__device__ float g_lrup[NB*IMG];
__device__ float g_key [NB*IMG];
__device__ float g_val [NB*IMG];
__device__ float g_qry [NB*IMG];
__device__ float g_s4  [NSPLIT*NB*2*9*PLANE];   // partial gating tap maps
__device__ float g_psim[NB*NGRP*25*PLANE];      // partial sims (26MB, L2-resident)
__device__ float g_w   [NB*25*PLANE];           // gated softmax weights

#define CP_COMMIT() asm volatile("cp.async.commit_group;")
#define CP_WAIT1()  asm volatile("cp.async.wait_group 1;")
#define CP_WAIT0()  asm volatile("cp.async.wait_group 0;")

// ---------------------------------------------------------------------------
// Kernel 1: fused bilinear upsample + three depthwise 3x3 convs.
// 4 horizontal px/thread. lr_up halo computed inline (bit-identical formula);
// center lr_up written out for k_agg.
// ---------------------------------------------------------------------------
__global__ __launch_bounds__(128) void k_qkv(const float* __restrict__ hr,
                      const float* __restrict__ lr,
                      const float* __restrict__ wq, const float* __restrict__ bq,
                      const float* __restrict__ wk, const float* __restrict__ bk,
                      const float* __restrict__ wv, const float* __restrict__ bv) {
    int idx = blockIdx.x * 128 + threadIdx.x;   // (n, c, h, w4)
    int w4 = idx & 31;
    int h  = (idx >> 5) & (HH-1);
    int c  = (idx >> 12) & (CH-1);
    int n  = idx >> 19;
    int w0 = w4 * 4;

    const float* ph = hr + (n*CH + c) * PLANE;
    const float* pl = lr + (n*CH + c) * (HL*WL);

    // column bilinear params for the 6 halo columns (wc = w0-1 .. w0+4)
    int cx0[6], cx1[6]; float cwx[6]; bool cvd[6];
    #pragma unroll
    for (int j = 0; j < 6; j++) {
        int wc = w0 + j - 1;
        cvd[j] = (wc >= 0) && (wc < WW);
        int wcc = cvd[j] ? wc : 0;
        float xs = (float)(wcc * (WL-1)) / (float)(WW-1);
        int x0 = (int)floorf(xs);
        cx0[j] = x0;
        cx1[j] = min(x0 + 1, WL-1);
        cwx[j] = xs - (float)x0;
    }

    float xh[3][6], xl[3][6];
    #pragma unroll
    for (int i = 0; i < 3; i++) {
        int hh = h + i - 1;
        bool hv = (hh >= 0) && (hh < HH);
        if (hv) {
            int rb = hh * WW;
            float lh = (w0 - 1 >= 0) ? ph[rb + w0 - 1] : 0.f;
            float4 mh = *(const float4*)&ph[rb + w0];
            float rh = (w0 + 4 < WW) ? ph[rb + w0 + 4] : 0.f;
            xh[i][0]=lh; xh[i][1]=mh.x; xh[i][2]=mh.y; xh[i][3]=mh.z; xh[i][4]=mh.w; xh[i][5]=rh;

            // bilinear row params (exact same expression as the old k_lrup)
            float ys = (float)(hh * (HL-1)) / (float)(HH-1);
            int y0 = (int)floorf(ys);
            int y1 = min(y0 + 1, HL-1);
            float wy = ys - (float)y0;
            const float* r0 = pl + y0*WL;
            const float* r1 = pl + y1*WL;
            #pragma unroll
            for (int j = 0; j < 6; j++) {
                if (cvd[j]) {
                    float a = r0[cx0[j]];
                    float b = r0[cx1[j]];
                    float cc = r1[cx0[j]];
                    float d = r1[cx1[j]];
                    float top = a + (b - a) * cwx[j];
                    float bot = cc + (d - cc) * cwx[j];
                    xl[i][j] = top + (bot - top) * wy;
                } else {
                    xl[i][j] = 0.f;
                }
            }
        } else {
            #pragma unroll
            for (int j = 0; j < 6; j++) { xh[i][j] = 0.f; xl[i][j] = 0.f; }
        }
    }

    float wkr[9], wvr[9], wqr[9];
    #pragma unroll
    for (int t = 0; t < 9; t++) {
        wkr[t] = wk[c*9 + t];
        wvr[t] = wv[c*9 + t];
        wqr[t] = wq[c*9 + t];
    }
    float bkc = bk[c], bvc = bv[c], bqc = bq[c];

    float4 ok, ov, oq;
    float* okp = (float*)&ok; float* ovp = (float*)&ov; float* oqp = (float*)&oq;
    #pragma unroll
    for (int p = 0; p < 4; p++) {
        float acck = bkc, accv = bvc, accq = bqc;
        #pragma unroll
        for (int i = 0; i < 3; i++)
            #pragma unroll
            for (int j = 0; j < 3; j++) {
                acck += xh[i][p+j] * wkr[i*3+j];
                accv += xh[i][p+j] * wvr[i*3+j];
                accq += xl[i][p+j] * wqr[i*3+j];
            }
        okp[p] = acck; ovp[p] = accv; oqp[p] = accq;
    }
    int gi = ((n*CH + c) << 14) + h*WW + w0;
    *(float4*)&g_key[gi] = ok;
    *(float4*)&g_val[gi] = ov;
    *(float4*)&g_qry[gi] = oq;

    // center lr_up (row i=1, cols j=1..4) for k_agg's output add
    float4 olu;
    olu.x = xl[1][1]; olu.y = xl[1][2]; olu.z = xl[1][3]; olu.w = xl[1][4];
    *(float4*)&g_lrup[gi] = olu;
}

// ---------------------------------------------------------------------------
// Kernel 2: partial gating tap maps, 4-way channel split, 2 px/thread.
// ---------------------------------------------------------------------------
__global__ __launch_bounds__(128) void k_s(const float* __restrict__ wa) {
    __shared__ __align__(16) float swa[CPS*36];   // 4.5 KB

    int tid = threadIdx.x;
    int sp  = blockIdx.y;
    int cbase = sp * CPS;

    for (int j = tid; j < CPS*36; j += 128) {
        int c   = j / 36;
        int r   = j % 36;
        int grp = r / 9;             // 0:q/o0 1:k/o0 2:q/o1 3:k/o1
        int t   = r % 9;
        int o   = grp >> 1;
        int ci  = cbase + c + ((grp & 1) ? CH : 0);
        swa[j] = wa[(o*2*CH + ci)*9 + t];
    }
    __syncthreads();

    int px0 = blockIdx.x * 256 + tid;           // pixel A
    int px1 = px0 + 128;                        // pixel B (same n: 256|16384)
    int n   = px0 >> 14;
    int pixA = px0 & (PLANE-1);
    int pixB = px1 & (PLANE-1);

    float accA[18], accB[18];
    #pragma unroll
    for (int t = 0; t < 18; t++) { accA[t] = 0.f; accB[t] = 0.f; }

    int baseA = n*CH*PLANE + cbase*PLANE + pixA;
    int baseB = n*CH*PLANE + cbase*PLANE + pixB;
    for (int c = 0; c < CPS; c++) {
        float qA = g_qry[baseA + c*PLANE];
        float kA = g_key[baseA + c*PLANE];
        float qB = g_qry[baseB + c*PLANE];
        float kB = g_key[baseB + c*PLANE];

        float wreg[36];
        float4* wr4 = (float4*)wreg;
        const float4* sw4 = (const float4*)(swa + c*36);
        #pragma unroll
        for (int i = 0; i < 9; i++) wr4[i] = sw4[i];

        #pragma unroll
        for (int t = 0; t < 9; t++) {
            accA[t]     += qA * wreg[t]    + kA * wreg[9+t];
            accA[9 + t] += qA * wreg[18+t] + kA * wreg[27+t];
            accB[t]     += qB * wreg[t]    + kB * wreg[9+t];
            accB[9 + t] += qB * wreg[18+t] + kB * wreg[27+t];
        }
    }

    #pragma unroll
    for (int o = 0; o < 2; o++)
        #pragma unroll
        for (int t = 0; t < 9; t++) {
            int s = (((sp*NB + n)*2 + o)*9 + t) << 14;
            g_s4[s + pixA] = accA[o*9 + t];
            g_s4[s + pixB] = accB[o*9 + t];
        }
}

// ---------------------------------------------------------------------------
// Tile geometry for window kernels: 64x8 px, 256 threads, warp = pixel row.
// SMEM column xx maps to gw = w0 + xx - 4  (halo of 4 on the left so every
// 16B cp.async is either fully in-range or fully out-of-range).
// ---------------------------------------------------------------------------
#define STW 64
#define STH 8
#define SHW 72        // 64 + 4 halo left + 4 halo right (float4-aligned)
#define SHH (STH+4)   // 12

// cp.async halo fill for an 8-channel chunk: 8*12 rows x 18 float4 = 1728 copies.
__device__ __forceinline__ void fill_async8(float st[GSIM][SHH][SHW],
                                            const float* gsrc, int nc_base,
                                            int cb, int h0, int w0, int tid) {
    const int NE = 8*12*18;
    #pragma unroll 1
    for (int i = tid; i < NE; i += 256) {
        int c  = i / 216;            // 12*18
        int r  = i - c*216;
        int yy = r / 18;
        int j  = r - yy*18;
        int gh = h0 + yy - 2;
        int gw = w0 + 4*j - 4;
        bool v = (gh >= 0) && (gh < HH) && (gw >= 0) && (gw < WW);
        int off = v ? (gh*WW + gw) : 0;
        const float* gp = gsrc + ((nc_base + cb + c) << 14) + off;
        uint32_t sa = (uint32_t)__cvta_generic_to_shared(&st[cb + c][yy][4*j]);
        int sz = v ? 16 : 0;
        asm volatile("cp.async.cg.shared.global [%0], [%1], 16, %2;"
                     :: "r"(sa), "l"(gp), "r"(sz));
    }
}

// ---------------------------------------------------------------------------
// Kernel 3: partial similarities, 16-ch group, dy-outer, 2 px/thread.
// cp.async fill, single wait, proven compute (R15 config, unchanged).
// ---------------------------------------------------------------------------
__global__ __launch_bounds__(256,4) void k_sim() {
    __shared__ __align__(16) float st[GSIM][SHH][SHW];   // 55.3 KB

    int tid  = threadIdx.x;
    int lane = tid & 31;
    int warp = tid >> 5;
    int w0 = blockIdx.x * STW;
    int h0 = blockIdx.y * STH;
    int g  = blockIdx.z & (NGRP-1);
    int n  = blockIdx.z >> 3;
    int c0 = g * GSIM;
    int pixA = (h0 + warp)*WW + w0 + 2*lane;

    fill_async8(st, g_key, n*CH + c0, 0, h0, w0, tid);
    CP_COMMIT();
    fill_async8(st, g_key, n*CH + c0, 8, h0, w0, tid);
    CP_COMMIT();

    // q loads overlap the async fills
    float2 q2[GSIM];
    #pragma unroll
    for (int c = 0; c < GSIM; c++)
        q2[c] = *(const float2*)&g_qry[((n*CH + c0 + c) << 14) + pixA];

    CP_WAIT0();
    __syncthreads();

    #pragma unroll
    for (int dy = 0; dy < 5; dy++) {
        float sA[5], sB[5];
        #pragma unroll
        for (int t = 0; t < 5; t++) { sA[t] = 0.f; sB[t] = 0.f; }

        #pragma unroll
        for (int c = 0; c < GSIM; c++) {
            float2 t0 = *(float2*)&st[c][warp+dy][2*lane + 2];
            float2 t1 = *(float2*)&st[c][warp+dy][2*lane + 4];
            float2 t2 = *(float2*)&st[c][warp+dy][2*lane + 6];
            sA[0] += q2[c].x * t0.x;
            sA[1] += q2[c].x * t0.y;
            sA[2] += q2[c].x * t1.x;
            sA[3] += q2[c].x * t1.y;
            sA[4] += q2[c].x * t2.x;
            sB[0] += q2[c].y * t0.y;
            sB[1] += q2[c].y * t1.x;
            sB[2] += q2[c].y * t1.y;
            sB[3] += q2[c].y * t2.x;
            sB[4] += q2[c].y * t2.y;
        }

        #pragma unroll
        for (int dx = 0; dx < 5; dx++) {
            float2 o; o.x = sA[dx]; o.y = sB[dx];
            *(float2*)&g_psim[(((n*NGRP + g)*25 + dy*5 + dx) << 14) + pixA] = o;
        }
    }
}

// ---------------------------------------------------------------------------
// Kernel 4: fused gate + softmax, 2 px/thread (float2 psim reads).
//   dyn[o] = sigmoid(ba[o] + sum_sp sum_tap shift(s4))
//   w = dyn0 * softmax(sum_g psim);  w[12] += dyn1
// ---------------------------------------------------------------------------
__global__ __launch_bounds__(128) void k_smax(const float* __restrict__ ba) {
    int idx = blockIdx.x * 128 + threadIdx.x;     // covers 2 adjacent pixels
    int px  = idx * 2;
    int pix = px & (PLANE-1);                     // even
    int n   = px >> 14;
    int w = pix & (WW-1);                         // even
    int h = pix >> 7;

    // inline dyn for both pixels (A at w, B at w+1)
    float a0A = ba[0], a0B = ba[0];
    float a1A = ba[1], a1B = ba[1];
    #pragma unroll
    for (int sp = 0; sp < NSPLIT; sp++) {
        #pragma unroll
        for (int i = 0; i < 3; i++) {
            int hh = h + i - 1;
            if (hh < 0 || hh >= HH) continue;
            #pragma unroll
            for (int j = 0; j < 3; j++) {
                int wA = w + j - 1;           // pixel A's tap column
                int wB = w + j;               // pixel B's tap column
                #pragma unroll
                for (int o = 0; o < 2; o++) {
                    const float* pl = g_s4 + (((((sp*NB + n)*2 + o)*9 + (i*3 + j)) << 14) + hh*WW);
                    float vA = (wA >= 0 && wA < WW) ? pl[wA] : 0.f;
                    float vB = (wB < WW) ? pl[wB] : 0.f;
                    if (o == 0) { a0A += vA; a0B += vB; }
                    else        { a1A += vA; a1B += vB; }
                }
            }
        }
    }
    float d0A = 1.f / (1.f + __expf(-a0A));
    float d0B = 1.f / (1.f + __expf(-a0B));
    float d1A = 1.f / (1.f + __expf(-a1A));
    float d1B = 1.f / (1.f + __expf(-a1B));

    float sA[25], sB[25];
    #pragma unroll
    for (int k = 0; k < 25; k++) { sA[k] = 0.f; sB[k] = 0.f; }
    #pragma unroll
    for (int g = 0; g < NGRP; g++)
        #pragma unroll
        for (int k = 0; k < 25; k++) {
            float2 v = *(const float2*)&g_psim[(((n*NGRP + g)*25 + k) << 14) + pix];
            sA[k] += v.x; sB[k] += v.y;
        }

    float mA = sA[0], mB = sB[0];
    #pragma unroll
    for (int k = 1; k < 25; k++) { mA = fmaxf(mA, sA[k]); mB = fmaxf(mB, sB[k]); }
    float suA = 0.f, suB = 0.f;
    #pragma unroll
    for (int k = 0; k < 25; k++) {
        sA[k] = __expf(sA[k] - mA); suA += sA[k];
        sB[k] = __expf(sB[k] - mB); suB += sB[k];
    }

    float scA = d0A / suA;
    float scB = d0B / suB;
    #pragma unroll
    for (int k = 0; k < 25; k++) {
        float2 o;
        o.x = sA[k] * scA;
        o.y = sB[k] * scB;
        if (k == 12) { o.x += d1A; o.y += d1B; }
        *(float2*)&g_w[((n*25 + k) << 14) + pix] = o;
    }
}

// ---------------------------------------------------------------------------
// Kernel 5: value aggregation, dy-outer, 2 px/thread, cp.async double buffer.
// (R15 config, unchanged)
// ---------------------------------------------------------------------------
__device__ __forceinline__ void agg_chunk(const float st[GSIM][SHH][SHW], int cb,
                                          int n, int c0, int pixA,
                                          int warp, int lane,
                                          float* __restrict__ out) {
    float aA[8], aB[8];
    #pragma unroll
    for (int cc = 0; cc < 8; cc++) { aA[cc] = 0.f; aB[cc] = 0.f; }

    #pragma unroll
    for (int dy = 0; dy < 5; dy++) {
        float wgA[5], wgB[5];
        #pragma unroll
        for (int dx = 0; dx < 5; dx++) {
            float2 wv = *(const float2*)&g_w[((n*25 + dy*5 + dx) << 14) + pixA];
            wgA[dx] = wv.x; wgB[dx] = wv.y;
        }
        #pragma unroll
        for (int cc = 0; cc < 8; cc++) {
            int c = cb + cc;
            float2 t0 = *(const float2*)&st[c][warp+dy][2*lane + 2];
            float2 t1 = *(const float2*)&st[c][warp+dy][2*lane + 4];
            float2 t2 = *(const float2*)&st[c][warp+dy][2*lane + 6];
            aA[cc] += wgA[0]*t0.x + wgA[1]*t0.y + wgA[2]*t1.x + wgA[3]*t1.y + wgA[4]*t2.x;
            aB[cc] += wgB[0]*t0.y + wgB[1]*t1.x + wgB[2]*t1.y + wgB[3]*t2.x + wgB[4]*t2.y;
        }
    }

    #pragma unroll
    for (int cc = 0; cc < 8; cc++) {
        int gi = ((n*CH + c0 + cb + cc) << 14) + pixA;
        float2 lu = *(const float2*)&g_lrup[gi];
        float2 o; o.x = lu.x + aA[cc]; o.y = lu.y + aB[cc];
        *(float2*)&out[gi] = o;
    }
}

__global__ __launch_bounds__(256,4) void k_agg(float* __restrict__ out) {
    __shared__ __align__(16) float st[GSIM][SHH][SHW];   // 55.3 KB

    int tid  = threadIdx.x;
    int lane = tid & 31;
    int warp = tid >> 5;
    int w0 = blockIdx.x * STW;
    int h0 = blockIdx.y * STH;
    int g  = blockIdx.z & (NGRP-1);
    int n  = blockIdx.z >> 3;
    int c0 = g * GSIM;
    int pixA = (h0 + warp)*WW + w0 + 2*lane;

    fill_async8(st, g_val, n*CH + c0, 0, h0, w0, tid);
    CP_COMMIT();
    fill_async8(st, g_val, n*CH + c0, 8, h0, w0, tid);
    CP_COMMIT();

    CP_WAIT1();
    __syncthreads();
    agg_chunk(st, 0, n, c0, pixA, warp, lane, out);   // overlaps chunk-1 copies

    CP_WAIT0();
    __syncthreads();
    agg_chunk(st, 8, n, c0, pixA, warp, lane, out);
}

// ---------------------------------------------------------------------------
extern "C" void kernel_launch(void* const* d_in, const int* in_sizes, int n_in,
                              void* d_out, int out_size) {
    const float* hr = (const float*)d_in[0];
    const float* lr = (const float*)d_in[1];
    const float* wq = (const float*)d_in[2];
    const float* bq = (const float*)d_in[3];
    const float* wk = (const float*)d_in[4];
    const float* bk = (const float*)d_in[5];
    const float* wv = (const float*)d_in[6];
    const float* bv = (const float*)d_in[7];
    const float* wa = (const float*)d_in[8];
    const float* ba = (const float*)d_in[9];
    float* out = (float*)d_out;

    k_qkv <<<(NB*IMG/4)/128, 128>>>(hr, lr, wq, bq, wk, bk, wv, bv);
    k_s   <<<dim3((NB*PLANE/2)/128, NSPLIT), 128>>>(wa);
    k_sim <<<dim3(WW/STW, HH/STH, NB*NGRP), 256>>>();
    // k_smax now at position 4 -> ncu window profiles it this round
    k_smax<<<(NB*PLANE/2)/128, 128>>>(ba);
    k_agg <<<dim3(WW/STW, HH/STH, NB*NGRP), 256>>>(out);
}

// round 17
// speedup vs baseline: 1.1107x; 1.1107x over previous
#include <cuda_runtime.h>
#include <cstdint>
#include <math.h>

// Problem constants (fixed shapes from setup_inputs)
#define NB 2
#define CH 128
#define HH 128
#define WW 128
#define HL 64
#define WL 64
#define PLANE (HH*WW)          // 16384
#define IMG   (CH*PLANE)

#define NSPLIT 4               // channel splits for gating conv
#define CPS (CH/NSPLIT)        // 32
#define NGRP 8                 // channel groups for sim/agg
#define GSIM (CH/NGRP)         // 16

// Scratch (module-load allocated; no runtime allocs)
__device__ float g_lrup[NB*IMG];
__device__ float g_key [NB*IMG];
__device__ float g_val [NB*IMG];
__device__ float g_qry [NB*IMG];
__device__ float g_s4  [NSPLIT*NB*2*9*PLANE];   // partial gating tap maps
__device__ float g_sred[NB*2*9*PLANE];          // reduced gating tap maps
__device__ float g_psim[NB*NGRP*25*PLANE];      // partial sims (26MB, L2-resident)
__device__ float g_sim [NB*25*PLANE];           // reduced sims
__device__ float g_w   [NB*25*PLANE];           // gated softmax weights

#define CP_COMMIT() asm volatile("cp.async.commit_group;")
#define CP_WAIT1()  asm volatile("cp.async.wait_group 1;")
#define CP_WAIT0()  asm volatile("cp.async.wait_group 0;")

// ---------------------------------------------------------------------------
// Kernel 1: fused bilinear upsample + three depthwise 3x3 convs.
// 4 horizontal px/thread. lr_up halo computed inline (bit-identical formula);
// center lr_up written out for k_agg.
// ---------------------------------------------------------------------------
__global__ __launch_bounds__(128) void k_qkv(const float* __restrict__ hr,
                      const float* __restrict__ lr,
                      const float* __restrict__ wq, const float* __restrict__ bq,
                      const float* __restrict__ wk, const float* __restrict__ bk,
                      const float* __restrict__ wv, const float* __restrict__ bv) {
    int idx = blockIdx.x * 128 + threadIdx.x;   // (n, c, h, w4)
    int w4 = idx & 31;
    int h  = (idx >> 5) & (HH-1);
    int c  = (idx >> 12) & (CH-1);
    int n  = idx >> 19;
    int w0 = w4 * 4;

    const float* ph = hr + (n*CH + c) * PLANE;
    const float* pl = lr + (n*CH + c) * (HL*WL);

    // column bilinear params for the 6 halo columns (wc = w0-1 .. w0+4)
    int cx0[6], cx1[6]; float cwx[6]; bool cvd[6];
    #pragma unroll
    for (int j = 0; j < 6; j++) {
        int wc = w0 + j - 1;
        cvd[j] = (wc >= 0) && (wc < WW);
        int wcc = cvd[j] ? wc : 0;
        float xs = (float)(wcc * (WL-1)) / (float)(WW-1);
        int x0 = (int)floorf(xs);
        cx0[j] = x0;
        cx1[j] = min(x0 + 1, WL-1);
        cwx[j] = xs - (float)x0;
    }

    float xh[3][6], xl[3][6];
    #pragma unroll
    for (int i = 0; i < 3; i++) {
        int hh = h + i - 1;
        bool hv = (hh >= 0) && (hh < HH);
        if (hv) {
            int rb = hh * WW;
            float lh = (w0 - 1 >= 0) ? ph[rb + w0 - 1] : 0.f;
            float4 mh = *(const float4*)&ph[rb + w0];
            float rh = (w0 + 4 < WW) ? ph[rb + w0 + 4] : 0.f;
            xh[i][0]=lh; xh[i][1]=mh.x; xh[i][2]=mh.y; xh[i][3]=mh.z; xh[i][4]=mh.w; xh[i][5]=rh;

            // bilinear row params (exact same expression as the old k_lrup)
            float ys = (float)(hh * (HL-1)) / (float)(HH-1);
            int y0 = (int)floorf(ys);
            int y1 = min(y0 + 1, HL-1);
            float wy = ys - (float)y0;
            const float* r0 = pl + y0*WL;
            const float* r1 = pl + y1*WL;
            #pragma unroll
            for (int j = 0; j < 6; j++) {
                if (cvd[j]) {
                    float a = r0[cx0[j]];
                    float b = r0[cx1[j]];
                    float cc = r1[cx0[j]];
                    float d = r1[cx1[j]];
                    float top = a + (b - a) * cwx[j];
                    float bot = cc + (d - cc) * cwx[j];
                    xl[i][j] = top + (bot - top) * wy;
                } else {
                    xl[i][j] = 0.f;
                }
            }
        } else {
            #pragma unroll
            for (int j = 0; j < 6; j++) { xh[i][j] = 0.f; xl[i][j] = 0.f; }
        }
    }

    float wkr[9], wvr[9], wqr[9];
    #pragma unroll
    for (int t = 0; t < 9; t++) {
        wkr[t] = wk[c*9 + t];
        wvr[t] = wv[c*9 + t];
        wqr[t] = wq[c*9 + t];
    }
    float bkc = bk[c], bvc = bv[c], bqc = bq[c];

    float4 ok, ov, oq;
    float* okp = (float*)&ok; float* ovp = (float*)&ov; float* oqp = (float*)&oq;
    #pragma unroll
    for (int p = 0; p < 4; p++) {
        float acck = bkc, accv = bvc, accq = bqc;
        #pragma unroll
        for (int i = 0; i < 3; i++)
            #pragma unroll
            for (int j = 0; j < 3; j++) {
                acck += xh[i][p+j] * wkr[i*3+j];
                accv += xh[i][p+j] * wvr[i*3+j];
                accq += xl[i][p+j] * wqr[i*3+j];
            }
        okp[p] = acck; ovp[p] = accv; oqp[p] = accq;
    }
    int gi = ((n*CH + c) << 14) + h*WW + w0;
    *(float4*)&g_key[gi] = ok;
    *(float4*)&g_val[gi] = ov;
    *(float4*)&g_qry[gi] = oq;

    // center lr_up (row i=1, cols j=1..4) for k_agg's output add
    float4 olu;
    olu.x = xl[1][1]; olu.y = xl[1][2]; olu.z = xl[1][3]; olu.w = xl[1][4];
    *(float4*)&g_lrup[gi] = olu;
}

// ---------------------------------------------------------------------------
// Kernel 2: partial gating tap maps, 4-way channel split, 2 px/thread.
// ---------------------------------------------------------------------------
__global__ __launch_bounds__(128) void k_s(const float* __restrict__ wa) {
    __shared__ __align__(16) float swa[CPS*36];   // 4.5 KB

    int tid = threadIdx.x;
    int sp  = blockIdx.y;
    int cbase = sp * CPS;

    for (int j = tid; j < CPS*36; j += 128) {
        int c   = j / 36;
        int r   = j % 36;
        int grp = r / 9;             // 0:q/o0 1:k/o0 2:q/o1 3:k/o1
        int t   = r % 9;
        int o   = grp >> 1;
        int ci  = cbase + c + ((grp & 1) ? CH : 0);
        swa[j] = wa[(o*2*CH + ci)*9 + t];
    }
    __syncthreads();

    int px0 = blockIdx.x * 256 + tid;           // pixel A
    int px1 = px0 + 128;                        // pixel B (same n: 256|16384)
    int n   = px0 >> 14;
    int pixA = px0 & (PLANE-1);
    int pixB = px1 & (PLANE-1);

    float accA[18], accB[18];
    #pragma unroll
    for (int t = 0; t < 18; t++) { accA[t] = 0.f; accB[t] = 0.f; }

    int baseA = n*CH*PLANE + cbase*PLANE + pixA;
    int baseB = n*CH*PLANE + cbase*PLANE + pixB;
    for (int c = 0; c < CPS; c++) {
        float qA = g_qry[baseA + c*PLANE];
        float kA = g_key[baseA + c*PLANE];
        float qB = g_qry[baseB + c*PLANE];
        float kB = g_key[baseB + c*PLANE];

        float wreg[36];
        float4* wr4 = (float4*)wreg;
        const float4* sw4 = (const float4*)(swa + c*36);
        #pragma unroll
        for (int i = 0; i < 9; i++) wr4[i] = sw4[i];

        #pragma unroll
        for (int t = 0; t < 9; t++) {
            accA[t]     += qA * wreg[t]    + kA * wreg[9+t];
            accA[9 + t] += qA * wreg[18+t] + kA * wreg[27+t];
            accB[t]     += qB * wreg[t]    + kB * wreg[9+t];
            accB[9 + t] += qB * wreg[18+t] + kB * wreg[27+t];
        }
    }

    #pragma unroll
    for (int o = 0; o < 2; o++)
        #pragma unroll
        for (int t = 0; t < 9; t++) {
            int s = (((sp*NB + n)*2 + o)*9 + t) << 14;
            g_s4[s + pixA] = accA[o*9 + t];
            g_s4[s + pixB] = accB[o*9 + t];
        }
}

// ---------------------------------------------------------------------------
// Tile geometry for window kernels: 64x8 px, 256 threads, warp = pixel row.
// SMEM column xx maps to gw = w0 + xx - 4  (halo of 4 on the left so every
// 16B cp.async is either fully in-range or fully out-of-range).
// ---------------------------------------------------------------------------
#define STW 64
#define STH 8
#define SHW 72        // 64 + 4 halo left + 4 halo right (float4-aligned)
#define SHH (STH+4)   // 12

// cp.async halo fill for an 8-channel chunk: 8*12 rows x 18 float4 = 1728 copies.
__device__ __forceinline__ void fill_async8(float st[GSIM][SHH][SHW],
                                            const float* gsrc, int nc_base,
                                            int cb, int h0, int w0, int tid) {
    const int NE = 8*12*18;
    #pragma unroll 1
    for (int i = tid; i < NE; i += 256) {
        int c  = i / 216;            // 12*18
        int r  = i - c*216;
        int yy = r / 18;
        int j  = r - yy*18;
        int gh = h0 + yy - 2;
        int gw = w0 + 4*j - 4;
        bool v = (gh >= 0) && (gh < HH) && (gw >= 0) && (gw < WW);
        int off = v ? (gh*WW + gw) : 0;
        const float* gp = gsrc + ((nc_base + cb + c) << 14) + off;
        uint32_t sa = (uint32_t)__cvta_generic_to_shared(&st[cb + c][yy][4*j]);
        int sz = v ? 16 : 0;
        asm volatile("cp.async.cg.shared.global [%0], [%1], 16, %2;"
                     :: "r"(sa), "l"(gp), "r"(sz));
    }
}

// ---------------------------------------------------------------------------
// Kernel 3: partial similarities, 16-ch group, dy-outer, 2 px/thread.
// cp.async fill, single wait, proven compute (R15 config, unchanged).
// ---------------------------------------------------------------------------
__global__ __launch_bounds__(256,4) void k_sim() {
    __shared__ __align__(16) float st[GSIM][SHH][SHW];   // 55.3 KB

    int tid  = threadIdx.x;
    int lane = tid & 31;
    int warp = tid >> 5;
    int w0 = blockIdx.x * STW;
    int h0 = blockIdx.y * STH;
    int g  = blockIdx.z & (NGRP-1);
    int n  = blockIdx.z >> 3;
    int c0 = g * GSIM;
    int pixA = (h0 + warp)*WW + w0 + 2*lane;

    fill_async8(st, g_key, n*CH + c0, 0, h0, w0, tid);
    CP_COMMIT();
    fill_async8(st, g_key, n*CH + c0, 8, h0, w0, tid);
    CP_COMMIT();

    // q loads overlap the async fills
    float2 q2[GSIM];
    #pragma unroll
    for (int c = 0; c < GSIM; c++)
        q2[c] = *(const float2*)&g_qry[((n*CH + c0 + c) << 14) + pixA];

    CP_WAIT0();
    __syncthreads();

    #pragma unroll
    for (int dy = 0; dy < 5; dy++) {
        float sA[5], sB[5];
        #pragma unroll
        for (int t = 0; t < 5; t++) { sA[t] = 0.f; sB[t] = 0.f; }

        #pragma unroll
        for (int c = 0; c < GSIM; c++) {
            float2 t0 = *(float2*)&st[c][warp+dy][2*lane + 2];
            float2 t1 = *(float2*)&st[c][warp+dy][2*lane + 4];
            float2 t2 = *(float2*)&st[c][warp+dy][2*lane + 6];
            sA[0] += q2[c].x * t0.x;
            sA[1] += q2[c].x * t0.y;
            sA[2] += q2[c].x * t1.x;
            sA[3] += q2[c].x * t1.y;
            sA[4] += q2[c].x * t2.x;
            sB[0] += q2[c].y * t0.y;
            sB[1] += q2[c].y * t1.x;
            sB[2] += q2[c].y * t1.y;
            sB[3] += q2[c].y * t2.x;
            sB[4] += q2[c].y * t2.y;
        }

        #pragma unroll
        for (int dx = 0; dx < 5; dx++) {
            float2 o; o.x = sA[dx]; o.y = sB[dx];
            *(float2*)&g_psim[(((n*NGRP + g)*25 + dy*5 + dx) << 14) + pixA] = o;
        }
    }
}

// ---------------------------------------------------------------------------
// Kernel 4: streaming reductions (massively parallel, float4 granularity).
//   Region 1: g_sim[n][k][pix]  = sum_g  g_psim[n][g][k][pix]   (204800 elems)
//   Region 2: g_sred[n][ot][pix]= sum_sp g_s4[sp][n][ot][pix]   ( 36864 elems)
// ---------------------------------------------------------------------------
#define RED1 (NB*25*PLANE/4)       // 204800
#define RED2 (NB*2*9*PLANE/4)      // 36864
#define REDT (RED1+RED2)           // 241664 = 944 * 256

__global__ __launch_bounds__(256) void k_red() {
    int i = blockIdx.x * 256 + threadIdx.x;
    if (i < RED1) {
        int nk  = i >> 12;                 // n*25 + k   (PLANE/4 = 4096)
        int pix = (i & 4095) << 2;
        int n   = nk / 25;
        int k   = nk - n*25;
        float4 acc = make_float4(0.f, 0.f, 0.f, 0.f);
        #pragma unroll
        for (int g = 0; g < NGRP; g++) {
            float4 v = *(const float4*)&g_psim[(((n*NGRP + g)*25 + k) << 14) + pix];
            acc.x += v.x; acc.y += v.y; acc.z += v.z; acc.w += v.w;
        }
        *(float4*)&g_sim[(nk << 14) + pix] = acc;
    } else {
        int j   = i - RED1;
        int nt  = j >> 12;                 // n*18 + ot
        int pix = (j & 4095) << 2;
        int n   = nt / 18;
        int ot  = nt - n*18;
        float4 acc = make_float4(0.f, 0.f, 0.f, 0.f);
        #pragma unroll
        for (int sp = 0; sp < NSPLIT; sp++) {
            float4 v = *(const float4*)&g_s4[(((sp*NB + n)*18 + ot) << 14) + pix];
            acc.x += v.x; acc.y += v.y; acc.z += v.z; acc.w += v.w;
        }
        *(float4*)&g_sred[(nt << 14) + pix] = acc;
    }
}

// ---------------------------------------------------------------------------
// Kernel 5: gate + softmax on reduced tensors, 1 px/thread.
//   dyn[o] = sigmoid(ba[o] + sum_tap shift(g_sred))
//   w = dyn0 * softmax(g_sim);  w[12] += dyn1
// ---------------------------------------------------------------------------
__global__ __launch_bounds__(128) void k_smax(const float* __restrict__ ba) {
    int idx = blockIdx.x * 128 + threadIdx.x;     // (n, pix)
    int pix = idx & (PLANE-1);
    int n   = idx >> 14;
    int w = pix & (WW-1);
    int h = pix >> 7;

    float acc0 = ba[0];
    float acc1 = ba[1];
    #pragma unroll
    for (int i = 0; i < 3; i++) {
        int hh = h + i - 1;
        if (hh < 0 || hh >= HH) continue;
        #pragma unroll
        for (int j = 0; j < 3; j++) {
            int ww2 = w + j - 1;
            if (ww2 < 0 || ww2 >= WW) continue;
            int t = i*3 + j;
            int off = hh*WW + ww2;
            acc0 += g_sred[((n*18 + t) << 14) + off];
            acc1 += g_sred[((n*18 + 9 + t) << 14) + off];
        }
    }
    float d0 = 1.f / (1.f + __expf(-acc0));
    float d1 = 1.f / (1.f + __expf(-acc1));

    float s[25];
    #pragma unroll
    for (int k = 0; k < 25; k++)
        s[k] = g_sim[((n*25 + k) << 14) + pix];

    float m = s[0];
    #pragma unroll
    for (int k = 1; k < 25; k++) m = fmaxf(m, s[k]);
    float ssum = 0.f;
    #pragma unroll
    for (int k = 0; k < 25; k++) { s[k] = __expf(s[k] - m); ssum += s[k]; }

    float scale = d0 / ssum;
    #pragma unroll
    for (int k = 0; k < 25; k++) {
        float wv = s[k] * scale;
        if (k == 12) wv += d1;
        g_w[((n*25 + k) << 14) + pix] = wv;
    }
}

// ---------------------------------------------------------------------------
// Kernel 6: value aggregation, dy-outer, 2 px/thread, cp.async double buffer.
// (R15 config, unchanged)
// ---------------------------------------------------------------------------
__device__ __forceinline__ void agg_chunk(const float st[GSIM][SHH][SHW], int cb,
                                          int n, int c0, int pixA,
                                          int warp, int lane,
                                          float* __restrict__ out) {
    float aA[8], aB[8];
    #pragma unroll
    for (int cc = 0; cc < 8; cc++) { aA[cc] = 0.f; aB[cc] = 0.f; }

    #pragma unroll
    for (int dy = 0; dy < 5; dy++) {
        float wgA[5], wgB[5];
        #pragma unroll
        for (int dx = 0; dx < 5; dx++) {
            float2 wv = *(const float2*)&g_w[((n*25 + dy*5 + dx) << 14) + pixA];
            wgA[dx] = wv.x; wgB[dx] = wv.y;
        }
        #pragma unroll
        for (int cc = 0; cc < 8; cc++) {
            int c = cb + cc;
            float2 t0 = *(const float2*)&st[c][warp+dy][2*lane + 2];
            float2 t1 = *(const float2*)&st[c][warp+dy][2*lane + 4];
            float2 t2 = *(const float2*)&st[c][warp+dy][2*lane + 6];
            aA[cc] += wgA[0]*t0.x + wgA[1]*t0.y + wgA[2]*t1.x + wgA[3]*t1.y + wgA[4]*t2.x;
            aB[cc] += wgB[0]*t0.y + wgB[1]*t1.x + wgB[2]*t1.y + wgB[3]*t2.x + wgB[4]*t2.y;
        }
    }

    #pragma unroll
    for (int cc = 0; cc < 8; cc++) {
        int gi = ((n*CH + c0 + cb + cc) << 14) + pixA;
        float2 lu = *(const float2*)&g_lrup[gi];
        float2 o; o.x = lu.x + aA[cc]; o.y = lu.y + aB[cc];
        *(float2*)&out[gi] = o;
    }
}

__global__ __launch_bounds__(256,4) void k_agg(float* __restrict__ out) {
    __shared__ __align__(16) float st[GSIM][SHH][SHW];   // 55.3 KB

    int tid  = threadIdx.x;
    int lane = tid & 31;
    int warp = tid >> 5;
    int w0 = blockIdx.x * STW;
    int h0 = blockIdx.y * STH;
    int g  = blockIdx.z & (NGRP-1);
    int n  = blockIdx.z >> 3;
    int c0 = g * GSIM;
    int pixA = (h0 + warp)*WW + w0 + 2*lane;

    fill_async8(st, g_val, n*CH + c0, 0, h0, w0, tid);
    CP_COMMIT();
    fill_async8(st, g_val, n*CH + c0, 8, h0, w0, tid);
    CP_COMMIT();

    CP_WAIT1();
    __syncthreads();
    agg_chunk(st, 0, n, c0, pixA, warp, lane, out);   // overlaps chunk-1 copies

    CP_WAIT0();
    __syncthreads();
    agg_chunk(st, 8, n, c0, pixA, warp, lane, out);
}

// ---------------------------------------------------------------------------
extern "C" void kernel_launch(void* const* d_in, const int* in_sizes, int n_in,
                              void* d_out, int out_size) {
    const float* hr = (const float*)d_in[0];
    const float* lr = (const float*)d_in[1];
    const float* wq = (const float*)d_in[2];
    const float* bq = (const float*)d_in[3];
    const float* wk = (const float*)d_in[4];
    const float* bk = (const float*)d_in[5];
    const float* wv = (const float*)d_in[6];
    const float* bv = (const float*)d_in[7];
    const float* wa = (const float*)d_in[8];
    const float* ba = (const float*)d_in[9];
    float* out = (float*)d_out;

    k_qkv <<<(NB*IMG/4)/128, 128>>>(hr, lr, wq, bq, wk, bk, wv, bv);
    k_s   <<<dim3((NB*PLANE/2)/128, NSPLIT), 128>>>(wa);
    k_sim <<<dim3(WW/STW, HH/STH, NB*NGRP), 256>>>();
    // k_red at position 4 -> ncu window profiles it this round
    k_red <<<REDT/256, 256>>>();
    k_smax<<<(NB*PLANE)/128, 128>>>(ba);
    k_agg <<<dim3(WW/STW, HH/STH, NB*NGRP), 256>>>(out);
}